// round 4
// baseline (speedup 1.0000x reference)
#include <cuda_runtime.h>
#include <cuda_bf16.h>

// HOG on GB300. ang = |atan2(gx, gy)| in [0,pi], bin = floor(ang*8/pi).
// Threshold form: ang >= k*pi/8  <=>  cot(k*pi/8)*|gx| - gy >= 0.
// R3: symmetric binning — only 3 boundary values t_k = |gy| - c_k*|gx|
// (c = 0.414, 1, 2.414) + predicate q=(gy<=0) reproduce all 7 thresholds:
//   upper (gy>0):  ang>=k pi/8 (k=1..3)  <=>  t_{4-k} <= 0
//   lower (gy<=0): ang>=k pi/8 (k=5..7)  <=>  t_{k-4} >= 0, and k=1..4 always.
// Accumulate U1..U3 (upper), N (all gy<=0), L5..L8 (lower); bins by differences.
// Vertical Sobel passes packed with f32x2 (FFMA2/FADD2) on aligned pairs.

using u64 = unsigned long long;

__device__ __forceinline__ u64 pk2(float lo, float hi) {
    u64 r; asm("mov.b64 %0, {%1, %2};" : "=l"(r) : "f"(lo), "f"(hi)); return r;
}
__device__ __forceinline__ void upk2(float& lo, float& hi, u64 v) {
    asm("mov.b64 {%0, %1}, %2;" : "=f"(lo), "=f"(hi) : "l"(v));
}
__device__ __forceinline__ u64 add2(u64 a, u64 b) {
    u64 r; asm("add.rn.f32x2 %0, %1, %2;" : "=l"(r) : "l"(a), "l"(b)); return r;
}
__device__ __forceinline__ u64 fma2(u64 a, u64 b, u64 c) {
    u64 r; asm("fma.rn.f32x2 %0, %1, %2, %3;" : "=l"(r) : "l"(a), "l"(b), "l"(c)); return r;
}
__device__ __forceinline__ float fsqrt_approx(float v) {
    float r; asm("sqrt.approx.f32 %0, %1;" : "=f"(r) : "f"(v)); return r;
}

struct Row { float eL; u64 m0, m1; float eR; };

__global__ void __launch_bounds__(256) hog_kernel(const float* __restrict__ x,
                                                  float* __restrict__ out) {
    const int t  = blockIdx.x * 256 + threadIdx.x;
    const int h  = t & 1;            // half of the cell (cols 0-3 / 4-7)
    const int cx = (t >> 1) & 63;
    const int cy = (t >> 7) & 63;
    const int b  = t >> 13;
    const int C  = (cx << 3) + (h << 2);   // first owned column
    const int R  = cy << 3;
    const float* img = x + (size_t)b * (512 * 512);
    const bool cL = (C > 0);
    const bool cR = (C < 508);

    const u64 TWO  = pk2(2.f, 2.f);
    const u64 MONE = pk2(-1.f, -1.f);

    Row rows[3];

#define LOAD_ROW(RI, rexpr)                                                    \
    {                                                                          \
        const int _r = (rexpr);                                                \
        if ((unsigned)_r < 512u) {                                             \
            const float* _p = img + _r * 512 + C;                              \
            rows[RI].eL = cL ? _p[-1] : 0.f;                                   \
            float4 _v = *(const float4*)(_p);                                  \
            rows[RI].m0 = pk2(_v.x, _v.y);                                     \
            rows[RI].m1 = pk2(_v.z, _v.w);                                     \
            rows[RI].eR = cR ? _p[4] : 0.f;                                    \
        } else {                                                               \
            rows[RI].eL = 0.f; rows[RI].m0 = 0ull;                             \
            rows[RI].m1 = 0ull; rows[RI].eR = 0.f;                             \
        }                                                                      \
    }

    float A0 = 0.f, U1 = 0.f, U2 = 0.f, U3 = 0.f, N = 0.f,
          L5 = 0.f, L6 = 0.f, L7 = 0.f, L8 = 0.f;

    LOAD_ROW(0, R - 1);
    LOAD_ROW(1, R);

#pragma unroll
    for (int rr = 0; rr < 8; rr++) {
        const int ia = rr % 3;          // row R+rr-1
        const int ib = (rr + 1) % 3;    // row R+rr
        const int ic = (rr + 2) % 3;    // row R+rr+1
        LOAD_ROW(ic, R + rr + 1);

        // vertical passes: s = [1,2,1], d = [-1,0,1]; packed for center cols
        u64 S0 = fma2(TWO, rows[ib].m0, add2(rows[ia].m0, rows[ic].m0));
        u64 S1 = fma2(TWO, rows[ib].m1, add2(rows[ia].m1, rows[ic].m1));
        u64 D0 = fma2(MONE, rows[ia].m0, rows[ic].m0);
        u64 D1 = fma2(MONE, rows[ia].m1, rows[ic].m1);
        float sL = fmaf(2.f, rows[ib].eL, rows[ia].eL + rows[ic].eL);
        float sR = fmaf(2.f, rows[ib].eR, rows[ia].eR + rows[ic].eR);
        float dL = rows[ic].eL - rows[ia].eL;
        float dR = rows[ic].eR - rows[ia].eR;

        float s0, s1, s2, s3, d0, d1, d2, d3;
        upk2(s0, s1, S0); upk2(s2, s3, S1);
        upk2(d0, d1, D0); upk2(d2, d3, D1);

        float gxv[4], gyv[4];
        gxv[0] = s1 - sL;  gyv[0] = fmaf(2.f, d0, dL + d1);
        gxv[1] = s2 - s0;  gyv[1] = fmaf(2.f, d1, d0 + d2);
        gxv[2] = s3 - s1;  gyv[2] = fmaf(2.f, d2, d1 + d3);
        gxv[3] = sR - s2;  gyv[3] = fmaf(2.f, d3, d2 + dR);

#pragma unroll
        for (int i = 0; i < 4; i++) {
            const float gx = gxv[i], gy = gyv[i];
            const float a  = fabsf(gx), u = fabsf(gy);
            const float mag = fsqrt_approx(fmaf(gx, gx, gy * gy));
            // t_k = |gy| - c_k*|gx|, c = {0.414, 1, 2.414}
            const float t1 = fmaf(-0.4142135623730951f, a, u);
            const float t2 = u - a;
            const float t3 = fmaf(-2.414213562373095f, a, u);
            const bool  q  = (gy <= 0.f);
            A0 += mag;
            if (q)               N  += mag;   // covers A1..A4 lower half
            if (!q && t3 <= 0.f) U1 += mag;   // ang >= 1*pi/8 (upper)
            if (!q && t2 <= 0.f) U2 += mag;   // ang >= 2*pi/8
            if (!q && t1 <= 0.f) U3 += mag;   // ang >= 3*pi/8
            if (q && t1 >= 0.f)  L5 += mag;   // ang >= 5*pi/8
            if (q && t2 >= 0.f)  L6 += mag;   // ang >= 6*pi/8
            if (q && t3 >= 0.f)  L7 += mag;   // ang >= 7*pi/8
            if (q && gx == 0.f)  L8 += mag;   // ang == pi (mag=0 if gy==0 too)
        }
    }
#undef LOAD_ROW

    // combine the two half-cell lanes (partner = lane^1)
    A0 += __shfl_xor_sync(0xFFFFFFFFu, A0, 1);
    U1 += __shfl_xor_sync(0xFFFFFFFFu, U1, 1);
    U2 += __shfl_xor_sync(0xFFFFFFFFu, U2, 1);
    U3 += __shfl_xor_sync(0xFFFFFFFFu, U3, 1);
    N  += __shfl_xor_sync(0xFFFFFFFFu, N,  1);
    L5 += __shfl_xor_sync(0xFFFFFFFFu, L5, 1);
    L6 += __shfl_xor_sync(0xFFFFFFFFu, L6, 1);
    L7 += __shfl_xor_sync(0xFFFFFFFFu, L7, 1);
    L8 += __shfl_xor_sync(0xFFFFFFFFu, L8, 1);

    // bins from prefix differences; split the 9 stores across the lane pair
    float* o = out + (size_t)b * (9 * 4096) + (cy << 6) + cx;
    if (h == 0) {
        o[0 * 4096] = A0 - (U1 + N);
        o[1 * 4096] = U1 - U2;
        o[2 * 4096] = U2 - U3;
        o[3 * 4096] = U3;
        o[4 * 4096] = N - L5;
    } else {
        o[5 * 4096] = L5 - L6;
        o[6 * 4096] = L6 - L7;
        o[7 * 4096] = L7 - L8;
        o[8 * 4096] = L8;
    }
}

extern "C" void kernel_launch(void* const* d_in, const int* in_sizes, int n_in,
                              void* d_out, int out_size) {
    const float* x = (const float*)d_in[0];
    float* out = (float*)d_out;
    // 64 batches * 64*64 cells * 2 half-cells = 524288 threads
    hog_kernel<<<2048, 256>>>(x, out);
}